// round 7
// baseline (speedup 1.0000x reference)
#include <cuda_runtime.h>
#include <cuda_fp16.h>
#include <cstdint>

// ============================================================================
// MotherCubeConv: y[n] = concat(x[n], x[nbr0..3(n)]) @ W^T + b
//   N=200000, F_in=128, fan_in=640, F_out=128.
// fp16 mma.sync. R7: CTA tile 64x128, 256 threads, 2 CTAs/SM (96KB smem each)
// so staging/barriers of one CTA hide under the other's MMA phase.
// W streamed double-buffered; gathered A staged via cp.async from prebuilt
// fp16 image of x. Warp tile 32x32 (no spills).
// ============================================================================

#define NSLOT 5
#define MAX_ROWS 200704

// ---- scratch (__device__ globals; no allocation allowed) -------------------
__device__ uint4 g_Wh[NSLOT * 2048];            // 5 x [128x128] fp16, swizzled
__device__ uint4 g_x16[(size_t)MAX_ROWS * 16];  // fp16 image of x (51.4MB)
__device__ int   g_is64;

// ---- helpers ----------------------------------------------------------------
__device__ __forceinline__ uint32_t smem_u32(const void* p) {
    uint32_t a;
    asm("{ .reg .u64 t; cvta.to.shared.u64 t, %1; cvt.u32.u64 %0, t; }"
        : "=r"(a) : "l"(p));
    return a;
}

__device__ __forceinline__ void ldsm_x4(uint32_t* r, uint32_t addr) {
    asm volatile("ldmatrix.sync.aligned.m8n8.x4.shared.b16 {%0,%1,%2,%3}, [%4];"
                 : "=r"(r[0]), "=r"(r[1]), "=r"(r[2]), "=r"(r[3]) : "r"(addr));
}

__device__ __forceinline__ void mma16816(float* d, const uint32_t* a,
                                         const uint32_t* b) {
    asm volatile(
        "mma.sync.aligned.m16n8k16.row.col.f32.f16.f16.f32 "
        "{%0,%1,%2,%3}, {%4,%5,%6,%7}, {%8,%9}, {%0,%1,%2,%3};"
        : "+f"(d[0]), "+f"(d[1]), "+f"(d[2]), "+f"(d[3])
        : "r"(a[0]), "r"(a[1]), "r"(a[2]), "r"(a[3]), "r"(b[0]), "r"(b[1]));
}

#define CP_ASYNC16(dst, src) \
    asm volatile("cp.async.cg.shared.global [%0], [%1], 16;" \
                 :: "r"(dst), "l"(src) : "memory")
#define CP_COMMIT() asm volatile("cp.async.commit_group;" ::: "memory")

// Swizzled byte offset: 256B row stride (16 groups of 16B), group XOR row&7.
__device__ __host__ __forceinline__ uint32_t tile_off(int row, int k) {
    uint32_t g = (uint32_t)(k >> 3);
    return (uint32_t)row * 256u + (((g ^ (uint32_t)(row & 7)) << 4)) +
           (uint32_t)(k & 7) * 2u;
}

// ---- fused prologue: cvt x -> fp16 image, W -> fp16 swizzled, dtype detect --
__global__ void prep_kernel(const float* __restrict__ x,
                            const float* __restrict__ W,
                            const int* __restrict__ nbr, int ngroups) {
    const int t = blockIdx.x * blockDim.x + threadIdx.x;
    if (t < ngroups) {
        const float4* s = (const float4*)x + (size_t)t * 2;
        float4 a = s[0], b = s[1];
        __half2 h0 = __floats2half2_rn(a.x, a.y);
        __half2 h1 = __floats2half2_rn(a.z, a.w);
        __half2 h2 = __floats2half2_rn(b.x, b.y);
        __half2 h3 = __floats2half2_rn(b.z, b.w);
        uint4 u;
        u.x = *(uint32_t*)&h0; u.y = *(uint32_t*)&h1;
        u.z = *(uint32_t*)&h2; u.w = *(uint32_t*)&h3;
        g_x16[t] = u;
    }
    if (t < NSLOT * 128 * 64) {
        int cp = t & 63;
        int f  = (t >> 6) & 127;
        int j  = t >> 13;
        int k  = cp * 2;
        __half2 h = __floats2half2_rn(W[f * 640 + j * 128 + k],
                                      W[f * 640 + j * 128 + k + 1]);
        *(uint32_t*)((char*)g_Wh + (size_t)j * 32768 + tile_off(f, k)) =
            *(uint32_t*)&h;
    }
    if (t == 0) {
        int all0 = 1;
        for (int i = 0; i < 64; i++)
            if (nbr[2 * i + 1] != 0) { all0 = 0; break; }
        g_is64 = all0;
    }
}

// ---- SMEM layout (per CTA: 97KB) ---------------------------------------------
static constexpr uint32_t OFF_BIAS = 0;        // 512B
static constexpr uint32_t OFF_W    = 1024;     // 2 x 32KB (streamed)
static constexpr uint32_t OFF_A    = 66560;    // 2 x 16KB (64-row tiles)
static constexpr uint32_t SMEM_BYTES = 99328;

__global__ void __launch_bounds__(256, 2)
mcconv_kernel(const void* __restrict__ nbr_raw,
              const float* __restrict__ bias_g, float* __restrict__ out, int N) {
    extern __shared__ char smem[];
    const uint32_t sb = smem_u32(smem);
    const int tid = threadIdx.x;
    const int wid = tid >> 5;
    const int lid = tid & 31;

    if (tid < 128) ((float*)(smem + OFF_BIAS))[tid] = bias_g[tid];

    // ---- per-thread gather assignment: 4 threads per row ----------------------
    const int row0 = blockIdx.x * 64;
    const int r    = tid >> 2;            // tile row 0..63
    const int c0   = (tid & 3) * 4;       // first of 4 16B-chunks (of 16)
    const int grow = row0 + r;
    const bool gvalid = grow < N;
    int idxs[NSLOT];
    idxs[0] = gvalid ? grow : 0;
    if (g_is64) {
        const long long* p = (const long long*)nbr_raw + (size_t)idxs[0] * 4;
        #pragma unroll
        for (int k = 0; k < 4; ++k) idxs[k + 1] = gvalid ? (int)p[k] : 0;
    } else {
        const int* p = (const int*)nbr_raw + (size_t)idxs[0] * 4;
        #pragma unroll
        for (int k = 0; k < 4; ++k) idxs[k + 1] = gvalid ? p[k] : 0;
    }

    // stage W slot j into buffer buf (32KB flat copy of pre-swizzled image)
    auto stage_W = [&](int j, int buf) {
        const char* src = (const char*)g_Wh + (size_t)j * 32768;
        const uint32_t dst = sb + OFF_W + (uint32_t)buf * 32768u;
        #pragma unroll
        for (int w = 0; w < 8; ++w) {
            const uint32_t e = (uint32_t)(tid + w * 256) * 16u;
            CP_ASYNC16(dst + e, src + e);
        }
    };
    // stage A slot j into buffer buf (16KB gather, swizzled dst)
    auto stage_A = [&](int j, int buf) {
        const char* src = (const char*)g_x16 + (size_t)idxs[j] * 256;
        const uint32_t dst = sb + OFF_A + (uint32_t)buf * 16384u;
        #pragma unroll
        for (int c = 0; c < 4; ++c) {
            const int chunk = c0 + c;
            CP_ASYNC16(dst + tile_off(r, chunk * 8), src + chunk * 16);
        }
    };

    stage_W(0, 0);
    stage_A(0, 0);
    CP_COMMIT();       // group: slot 0

    // warp tiling: 2 (M) x 4 (N); warp tile = 32 rows x 32 cols
    const int wm = wid >> 2;
    const int wn = wid & 3;

    float acc[2][4][4];
    #pragma unroll
    for (int mt = 0; mt < 2; ++mt)
        #pragma unroll
        for (int nt = 0; nt < 4; ++nt)
            #pragma unroll
            for (int q = 0; q < 4; ++q) acc[mt][nt][q] = 0.0f;

    // per-lane ldmatrix addressing
    const int a_row  = (lid & 15);
    const int a_gsel = (lid >> 4);
    const int b_row  = (lid & 7);
    const int b_ntin = (lid >> 4);        // which nt within a pair
    const int b_gsel = ((lid >> 3) & 1);  // k-group select

    #pragma unroll
    for (int j = 0; j < NSLOT; ++j) {
        if (j < NSLOT - 1) {
            stage_W(j + 1, (j + 1) & 1);
            stage_A(j + 1, (j + 1) & 1);
            CP_COMMIT();
            asm volatile("cp.async.wait_group 1;" ::: "memory");
        } else {
            asm volatile("cp.async.wait_group 0;" ::: "memory");
        }
        __syncthreads();   // W[j] + A[j] visible to all warps

        const uint32_t wbase = sb + OFF_W + (uint32_t)(j & 1) * 32768u;
        const uint32_t abase = sb + OFF_A + (uint32_t)(j & 1) * 16384u;

        #pragma unroll
        for (int kc = 0; kc < 8; ++kc) {
            // B frags: two x4 loads cover nt pairs {0,1},{2,3}
            uint32_t bh[4][2];
            #pragma unroll
            for (int p = 0; p < 2; ++p) {
                const int nr = wn * 32 + p * 16 + b_ntin * 8 + b_row;
                const int g  = kc * 2 + b_gsel;
                const uint32_t off =
                    (uint32_t)nr * 256u + (((uint32_t)(g ^ (nr & 7))) << 4);
                uint32_t rr[4];
                ldsm_x4(rr, wbase + off);
                bh[p * 2 + 0][0] = rr[0];
                bh[p * 2 + 0][1] = rr[1];
                bh[p * 2 + 1][0] = rr[2];
                bh[p * 2 + 1][1] = rr[3];
            }
            // A frags: one x4 per mt (2 m-tiles of 16 rows)
            const int gA = kc * 2 + a_gsel;
            #pragma unroll
            for (int mt = 0; mt < 2; ++mt) {
                const int ar = wm * 32 + mt * 16 + a_row;
                const uint32_t off =
                    (uint32_t)ar * 256u + (((uint32_t)(gA ^ (ar & 7))) << 4);
                uint32_t ah[4];
                ldsm_x4(ah, abase + off);
                #pragma unroll
                for (int nt = 0; nt < 4; ++nt)
                    mma16816(acc[mt][nt], ah, bh[nt]);
            }
        }
        if (j < NSLOT - 1) __syncthreads();   // reads done before next staging
    }

    // ---- epilogue --------------------------------------------------------------
    {
        const float* bs = (const float*)(smem + OFF_BIAS);
        const int rl = lid >> 2;
        const int cl = (lid & 3) * 2;
        #pragma unroll
        for (int mt = 0; mt < 2; ++mt) {
            const int r_base = row0 + wm * 32 + mt * 16 + rl;
            #pragma unroll
            for (int nt = 0; nt < 4; ++nt) {
                const int col = wn * 32 + nt * 8 + cl;
                const float b0 = bs[col], b1 = bs[col + 1];
                if (r_base < N) {
                    float2 vv = make_float2(acc[mt][nt][0] + b0,
                                            acc[mt][nt][1] + b1);
                    *(float2*)(out + (size_t)r_base * 128 + col) = vv;
                }
                if (r_base + 8 < N) {
                    float2 vv = make_float2(acc[mt][nt][2] + b0,
                                            acc[mt][nt][3] + b1);
                    *(float2*)(out + (size_t)(r_base + 8) * 128 + col) = vv;
                }
            }
        }
    }
}

// ---- launch ------------------------------------------------------------------
extern "C" void kernel_launch(void* const* d_in, const int* in_sizes, int n_in,
                              void* d_out, int out_size) {
    const float* x   = (const float*)d_in[0];
    const void*  nbr = d_in[1];
    const float* W   = (const float*)d_in[2];
    const float* b   = (const float*)d_in[3];
    float* out = (float*)d_out;
    const int N = in_sizes[0] / 128;
    const int tiles = (N + 63) / 64;
    const int ngroups = N * 16;   // 8 fp32 elems per group

    cudaFuncSetAttribute(mcconv_kernel,
                         cudaFuncAttributeMaxDynamicSharedMemorySize, SMEM_BYTES);

    prep_kernel<<<(ngroups + 255) / 256, 256>>>(x, W, (const int*)nbr, ngroups);
    mcconv_kernel<<<tiles, 256, SMEM_BYTES>>>(nbr, b, out, N);
}

// round 8
// speedup vs baseline: 1.1400x; 1.1400x over previous
#include <cuda_runtime.h>
#include <cuda_fp16.h>
#include <cstdint>

// ============================================================================
// MotherCubeConv: y[n] = concat(x[n], x[nbr0..3(n)]) @ W^T + b
//   N=200000, F_in=128, fan_in=640, F_out=128.
// fp16 mma.sync. R8: CTA 128x128 with 256 threads and 64x32 warp tiles
// (8 warps, 2x4). Cuts LDSM fragment traffic/MAC 25% vs 32x32 while keeping
// register use under the 255/thread ceiling (no spills). W fully SMEM-
// resident; gathered A double-buffered via cp.async from fp16 image of x.
// ============================================================================

#define NSLOT 5
#define MAX_ROWS 200704

// ---- scratch (__device__ globals; no allocation allowed) -------------------
__device__ uint4 g_Wh[NSLOT * 2048];            // 5 x [128x128] fp16, swizzled
__device__ uint4 g_x16[(size_t)MAX_ROWS * 16];  // fp16 image of x (51.4MB)
__device__ int   g_is64;

// ---- helpers ----------------------------------------------------------------
__device__ __forceinline__ uint32_t smem_u32(const void* p) {
    uint32_t a;
    asm("{ .reg .u64 t; cvta.to.shared.u64 t, %1; cvt.u32.u64 %0, t; }"
        : "=r"(a) : "l"(p));
    return a;
}

__device__ __forceinline__ void ldsm_x4(uint32_t* r, uint32_t addr) {
    asm volatile("ldmatrix.sync.aligned.m8n8.x4.shared.b16 {%0,%1,%2,%3}, [%4];"
                 : "=r"(r[0]), "=r"(r[1]), "=r"(r[2]), "=r"(r[3]) : "r"(addr));
}

__device__ __forceinline__ void mma16816(float* d, const uint32_t* a,
                                         const uint32_t* b) {
    asm volatile(
        "mma.sync.aligned.m16n8k16.row.col.f32.f16.f16.f32 "
        "{%0,%1,%2,%3}, {%4,%5,%6,%7}, {%8,%9}, {%0,%1,%2,%3};"
        : "+f"(d[0]), "+f"(d[1]), "+f"(d[2]), "+f"(d[3])
        : "r"(a[0]), "r"(a[1]), "r"(a[2]), "r"(a[3]), "r"(b[0]), "r"(b[1]));
}

#define CP_ASYNC16(dst, src) \
    asm volatile("cp.async.cg.shared.global [%0], [%1], 16;" \
                 :: "r"(dst), "l"(src) : "memory")
#define CP_COMMIT() asm volatile("cp.async.commit_group;" ::: "memory")

// Swizzled byte offset: 256B row stride (16 groups of 16B), group XOR row&7.
__device__ __host__ __forceinline__ uint32_t tile_off(int row, int k) {
    uint32_t g = (uint32_t)(k >> 3);
    return (uint32_t)row * 256u + (((g ^ (uint32_t)(row & 7)) << 4)) +
           (uint32_t)(k & 7) * 2u;
}

// ---- fused prologue: cvt x -> fp16 image, W -> fp16 swizzled, dtype detect --
__global__ void prep_kernel(const float* __restrict__ x,
                            const float* __restrict__ W,
                            const int* __restrict__ nbr, int ngroups) {
    const int t = blockIdx.x * blockDim.x + threadIdx.x;
    if (t < ngroups) {
        const float4* s = (const float4*)x + (size_t)t * 2;
        float4 a = s[0], b = s[1];
        __half2 h0 = __floats2half2_rn(a.x, a.y);
        __half2 h1 = __floats2half2_rn(a.z, a.w);
        __half2 h2 = __floats2half2_rn(b.x, b.y);
        __half2 h3 = __floats2half2_rn(b.z, b.w);
        uint4 u;
        u.x = *(uint32_t*)&h0; u.y = *(uint32_t*)&h1;
        u.z = *(uint32_t*)&h2; u.w = *(uint32_t*)&h3;
        g_x16[t] = u;
    }
    if (t < NSLOT * 128 * 64) {
        int cp = t & 63;
        int f  = (t >> 6) & 127;
        int j  = t >> 13;
        int k  = cp * 2;
        __half2 h = __floats2half2_rn(W[f * 640 + j * 128 + k],
                                      W[f * 640 + j * 128 + k + 1]);
        *(uint32_t*)((char*)g_Wh + (size_t)j * 32768 + tile_off(f, k)) =
            *(uint32_t*)&h;
    }
    if (t == 0) {
        int all0 = 1;
        for (int i = 0; i < 64; i++)
            if (nbr[2 * i + 1] != 0) { all0 = 0; break; }
        g_is64 = all0;
    }
}

// ---- SMEM layout --------------------------------------------------------------
static constexpr uint32_t OFF_BIAS = 0;        // 512B
static constexpr uint32_t OFF_W    = 1024;     // 5 x 32KB (resident)
static constexpr uint32_t OFF_A    = 164864;   // 2 x 32KB (128-row tiles)
static constexpr uint32_t SMEM_BYTES = 230400;

__global__ void __launch_bounds__(256, 1)
mcconv_kernel(const void* __restrict__ nbr_raw,
              const float* __restrict__ bias_g, float* __restrict__ out, int N) {
    extern __shared__ char smem[];
    const uint32_t sb = smem_u32(smem);
    const int tid = threadIdx.x;
    const int wid = tid >> 5;
    const int lid = tid & 31;

    if (tid < 128) ((float*)(smem + OFF_BIAS))[tid] = bias_g[tid];

    // ---- stage all W (160KB) in one commit group ------------------------------
    {
        const char* src = (const char*)g_Wh;
        const uint32_t dst = sb + OFF_W;
        #pragma unroll
        for (int w = 0; w < 40; ++w) {
            const uint32_t e = (uint32_t)(tid + w * 256) * 16u;
            CP_ASYNC16(dst + e, src + e);
        }
        CP_COMMIT();   // group: W
    }

    // ---- per-thread gather assignment: 2 threads per row ----------------------
    const int row0 = blockIdx.x * 128;
    const int r    = tid >> 1;            // tile row 0..127
    const int c0   = (tid & 1) * 8;       // first of 8 16B-chunks (of 16)
    const int grow = row0 + r;
    const bool gvalid = grow < N;
    int idxs[NSLOT];
    idxs[0] = gvalid ? grow : 0;
    if (g_is64) {
        const long long* p = (const long long*)nbr_raw + (size_t)idxs[0] * 4;
        #pragma unroll
        for (int k = 0; k < 4; ++k) idxs[k + 1] = gvalid ? (int)p[k] : 0;
    } else {
        const int* p = (const int*)nbr_raw + (size_t)idxs[0] * 4;
        #pragma unroll
        for (int k = 0; k < 4; ++k) idxs[k + 1] = gvalid ? p[k] : 0;
    }

    // stage A slot j into buffer buf (32KB gather, swizzled dst)
    auto stage_A = [&](int j, int buf) {
        const char* src = (const char*)g_x16 + (size_t)idxs[j] * 256;
        const uint32_t dst = sb + OFF_A + (uint32_t)buf * 32768u;
        #pragma unroll
        for (int c = 0; c < 8; ++c) {
            const int chunk = c0 + c;
            CP_ASYNC16(dst + tile_off(r, chunk * 8), src + chunk * 16);
        }
    };

    stage_A(0, 0);
    CP_COMMIT();       // group: A0

    // warp tiling: 2 (M) x 4 (N); warp tile = 64 rows x 32 cols
    const int wm = wid >> 2;
    const int wn = wid & 3;

    float acc[4][4][4];   // [mt 16-row][nt 8-col][reg]
    #pragma unroll
    for (int mt = 0; mt < 4; ++mt)
        #pragma unroll
        for (int nt = 0; nt < 4; ++nt)
            #pragma unroll
            for (int q = 0; q < 4; ++q) acc[mt][nt][q] = 0.0f;

    // per-lane ldmatrix addressing
    const int a_row  = (lid & 15);
    const int a_gsel = (lid >> 4);
    const int b_row  = (lid & 7);
    const int b_ntin = (lid >> 4);        // which nt within a pair
    const int b_gsel = ((lid >> 3) & 1);  // k-group select

    #pragma unroll
    for (int j = 0; j < NSLOT; ++j) {
        if (j < NSLOT - 1) {
            stage_A(j + 1, (j + 1) & 1);
            CP_COMMIT();
            asm volatile("cp.async.wait_group 1;" ::: "memory");
        } else {
            asm volatile("cp.async.wait_group 0;" ::: "memory");
        }
        __syncthreads();   // W + A[j] visible to all warps

        const uint32_t wbase = sb + OFF_W + (uint32_t)j * 32768u;
        const uint32_t abase = sb + OFF_A + (uint32_t)(j & 1) * 32768u;

        #pragma unroll
        for (int kc = 0; kc < 8; ++kc) {
            // B frags: two x4 loads cover nt pairs {0,1},{2,3}
            uint32_t bh[4][2];
            #pragma unroll
            for (int p = 0; p < 2; ++p) {
                const int nr = wn * 32 + p * 16 + b_ntin * 8 + b_row;
                const int g  = kc * 2 + b_gsel;
                const uint32_t off =
                    (uint32_t)nr * 256u + (((uint32_t)(g ^ (nr & 7))) << 4);
                uint32_t rr[4];
                ldsm_x4(rr, wbase + off);
                bh[p * 2 + 0][0] = rr[0];
                bh[p * 2 + 0][1] = rr[1];
                bh[p * 2 + 1][0] = rr[2];
                bh[p * 2 + 1][1] = rr[3];
            }
            // A frags: one x4 per mt (4 m-tiles of 16 rows)
            const int gA = kc * 2 + a_gsel;
            #pragma unroll
            for (int mt = 0; mt < 4; ++mt) {
                const int ar = wm * 64 + mt * 16 + a_row;
                const uint32_t off =
                    (uint32_t)ar * 256u + (((uint32_t)(gA ^ (ar & 7))) << 4);
                uint32_t ah[4];
                ldsm_x4(ah, abase + off);
                #pragma unroll
                for (int nt = 0; nt < 4; ++nt)
                    mma16816(acc[mt][nt], ah, bh[nt]);
            }
        }
        if (j < NSLOT - 1) __syncthreads();   // reads done before next staging
    }

    // ---- epilogue --------------------------------------------------------------
    {
        const float* bs = (const float*)(smem + OFF_BIAS);
        const int rl = lid >> 2;
        const int cl = (lid & 3) * 2;
        #pragma unroll
        for (int mt = 0; mt < 4; ++mt) {
            const int r_base = row0 + wm * 64 + mt * 16 + rl;
            #pragma unroll
            for (int nt = 0; nt < 4; ++nt) {
                const int col = wn * 32 + nt * 8 + cl;
                const float b0 = bs[col], b1 = bs[col + 1];
                if (r_base < N) {
                    float2 vv = make_float2(acc[mt][nt][0] + b0,
                                            acc[mt][nt][1] + b1);
                    *(float2*)(out + (size_t)r_base * 128 + col) = vv;
                }
                if (r_base + 8 < N) {
                    float2 vv = make_float2(acc[mt][nt][2] + b0,
                                            acc[mt][nt][3] + b1);
                    *(float2*)(out + (size_t)(r_base + 8) * 128 + col) = vv;
                }
            }
        }
    }
}

// ---- launch ------------------------------------------------------------------
extern "C" void kernel_launch(void* const* d_in, const int* in_sizes, int n_in,
                              void* d_out, int out_size) {
    const float* x   = (const float*)d_in[0];
    const void*  nbr = d_in[1];
    const float* W   = (const float*)d_in[2];
    const float* b   = (const float*)d_in[3];
    float* out = (float*)d_out;
    const int N = in_sizes[0] / 128;
    const int tiles = (N + 127) / 128;
    const int ngroups = N * 16;   // 8 fp32 elems per group

    cudaFuncSetAttribute(mcconv_kernel,
                         cudaFuncAttributeMaxDynamicSharedMemorySize, SMEM_BYTES);

    prep_kernel<<<(ngroups + 255) / 256, 256>>>(x, W, (const int*)nbr, ngroups);
    mcconv_kernel<<<tiles, 256, SMEM_BYTES>>>(nbr, b, out, N);
}

// round 9
// speedup vs baseline: 1.3659x; 1.1982x over previous
#include <cuda_runtime.h>
#include <cuda_fp16.h>
#include <cstdint>

// ============================================================================
// MotherCubeConv: y[n] = concat(x[n], x[nbr0..3(n)]) @ W^T + b
//   N=200000, F_in=128, fan_in=640, F_out=128.
// fp16 mma.sync. R9: persistent CTAs (grid=148): W staged once per CTA,
// cross-tile cp.async pipelining (slot0 of tile t+1 staged during slot4 of
// tile t), epilogue overlapped with staging. Inner loop = R4 optimum:
// 512 threads, 32x32 warp tiles, A double-buffered from fp16 image of x.
// ============================================================================

#define NSLOT 5
#define MAX_ROWS 200704

// ---- scratch (__device__ globals; no allocation allowed) -------------------
__device__ uint4 g_Wh[NSLOT * 2048];            // 5 x [128x128] fp16, swizzled
__device__ uint4 g_x16[(size_t)MAX_ROWS * 16];  // fp16 image of x (51.4MB)
__device__ int   g_is64;

// ---- helpers ----------------------------------------------------------------
__device__ __forceinline__ uint32_t smem_u32(const void* p) {
    uint32_t a;
    asm("{ .reg .u64 t; cvta.to.shared.u64 t, %1; cvt.u32.u64 %0, t; }"
        : "=r"(a) : "l"(p));
    return a;
}

__device__ __forceinline__ void ldsm_x4(uint32_t* r, uint32_t addr) {
    asm volatile("ldmatrix.sync.aligned.m8n8.x4.shared.b16 {%0,%1,%2,%3}, [%4];"
                 : "=r"(r[0]), "=r"(r[1]), "=r"(r[2]), "=r"(r[3]) : "r"(addr));
}
__device__ __forceinline__ void ldsm_x2(uint32_t* r, uint32_t addr) {
    asm volatile("ldmatrix.sync.aligned.m8n8.x2.shared.b16 {%0,%1}, [%2];"
                 : "=r"(r[0]), "=r"(r[1]) : "r"(addr));
}

__device__ __forceinline__ void mma16816(float* d, const uint32_t* a,
                                         const uint32_t* b) {
    asm volatile(
        "mma.sync.aligned.m16n8k16.row.col.f32.f16.f16.f32 "
        "{%0,%1,%2,%3}, {%4,%5,%6,%7}, {%8,%9}, {%0,%1,%2,%3};"
        : "+f"(d[0]), "+f"(d[1]), "+f"(d[2]), "+f"(d[3])
        : "r"(a[0]), "r"(a[1]), "r"(a[2]), "r"(a[3]), "r"(b[0]), "r"(b[1]));
}

#define CP_ASYNC16(dst, src) \
    asm volatile("cp.async.cg.shared.global [%0], [%1], 16;" \
                 :: "r"(dst), "l"(src) : "memory")
#define CP_COMMIT() asm volatile("cp.async.commit_group;" ::: "memory")

// Swizzled byte offset: 256B row stride (16 groups of 16B), group XOR row&7.
__device__ __host__ __forceinline__ uint32_t tile_off(int row, int k) {
    uint32_t g = (uint32_t)(k >> 3);
    return (uint32_t)row * 256u + (((g ^ (uint32_t)(row & 7)) << 4)) +
           (uint32_t)(k & 7) * 2u;
}

// ---- fused prologue: cvt x -> fp16 image, W -> fp16 swizzled, dtype detect --
__global__ void prep_kernel(const float* __restrict__ x,
                            const float* __restrict__ W,
                            const int* __restrict__ nbr, int ngroups) {
    const int t = blockIdx.x * blockDim.x + threadIdx.x;
    if (t < ngroups) {
        const float4* s = (const float4*)x + (size_t)t * 2;
        float4 a = s[0], b = s[1];
        __half2 h0 = __floats2half2_rn(a.x, a.y);
        __half2 h1 = __floats2half2_rn(a.z, a.w);
        __half2 h2 = __floats2half2_rn(b.x, b.y);
        __half2 h3 = __floats2half2_rn(b.z, b.w);
        uint4 u;
        u.x = *(uint32_t*)&h0; u.y = *(uint32_t*)&h1;
        u.z = *(uint32_t*)&h2; u.w = *(uint32_t*)&h3;
        g_x16[t] = u;
    }
    if (t < NSLOT * 128 * 64) {
        int cp = t & 63;
        int f  = (t >> 6) & 127;
        int j  = t >> 13;
        int k  = cp * 2;
        __half2 h = __floats2half2_rn(W[f * 640 + j * 128 + k],
                                      W[f * 640 + j * 128 + k + 1]);
        *(uint32_t*)((char*)g_Wh + (size_t)j * 32768 + tile_off(f, k)) =
            *(uint32_t*)&h;
    }
    if (t == 0) {
        int all0 = 1;
        for (int i = 0; i < 64; i++)
            if (nbr[2 * i + 1] != 0) { all0 = 0; break; }
        g_is64 = all0;
    }
}

// ---- SMEM layout --------------------------------------------------------------
static constexpr uint32_t OFF_BIAS = 0;        // 512B
static constexpr uint32_t OFF_W    = 1024;     // 5 x 32KB (resident)
static constexpr uint32_t OFF_A    = 164864;   // 2 x 32KB
static constexpr uint32_t SMEM_BYTES = 230400;

__global__ void __launch_bounds__(512, 1)
mcconv_kernel(const void* __restrict__ nbr_raw,
              const float* __restrict__ bias_g, float* __restrict__ out, int N) {
    extern __shared__ char smem[];
    const uint32_t sb = smem_u32(smem);
    const int tid = threadIdx.x;
    const int wid = tid >> 5;
    const int lid = tid & 31;
    const int ntiles = (N + 127) >> 7;

    if (tid < 128) ((float*)(smem + OFF_BIAS))[tid] = bias_g[tid];

    // ---- stage all W (160KB) once -----------------------------------------------
    {
        const char* src = (const char*)g_Wh;
        const uint32_t dst = sb + OFF_W;
        #pragma unroll
        for (int w = 0; w < 20; ++w) {
            const uint32_t e = (uint32_t)(tid + w * 512) * 16u;
            CP_ASYNC16(dst + e, src + e);
        }
    }

    const int r    = tid >> 2;            // tile row 0..127 this thread stages
    const int c0   = (tid & 3) * 4;       // first of 4 16B-chunks (of 16)
    const int is64 = g_is64;
    const long long* nbr64 = (const long long*)nbr_raw;
    const int*       nbr32 = (const int*)nbr_raw;

    auto load_idxs = [&](int tile, int* dst) {
        const int grow = tile * 128 + r;
        const bool v = grow < N;
        const int base = v ? grow : 0;
        dst[0] = base;
        if (is64) {
            const long long* p = nbr64 + (size_t)base * 4;
            #pragma unroll
            for (int k = 0; k < 4; ++k) dst[k + 1] = v ? (int)p[k] : 0;
        } else {
            const int* p = nbr32 + (size_t)base * 4;
            #pragma unroll
            for (int k = 0; k < 4; ++k) dst[k + 1] = v ? p[k] : 0;
        }
    };

    auto stage_A = [&](int src_row, int buf) {
        const char* src = (const char*)g_x16 + (size_t)src_row * 256;
        const uint32_t dst = sb + OFF_A + (uint32_t)buf * 32768u;
        #pragma unroll
        for (int c = 0; c < 4; ++c) {
            const int chunk = c0 + c;
            CP_ASYNC16(dst + tile_off(r, chunk * 8), src + chunk * 16);
        }
    };

    int idxs[NSLOT], nidxs[NSLOT];
    int tile = blockIdx.x;
    if (tile < ntiles) {
        load_idxs(tile, idxs);
        stage_A(idxs[0], 0);
    }
    CP_COMMIT();   // group: W + A(tile0, slot0)

    // warp tiling: 4 (M) x 4 (N); warp tile = 32 rows x 32 cols
    const int wm = wid >> 2;
    const int wn = wid & 3;

    float acc[2][4][4];
    #pragma unroll
    for (int mt = 0; mt < 2; ++mt)
        #pragma unroll
        for (int nt = 0; nt < 4; ++nt)
            #pragma unroll
            for (int q = 0; q < 4; ++q) acc[mt][nt][q] = 0.0f;

    const int a_row  = (lid & 15);
    const int a_gsel = (lid >> 4);
    const int b_row  = (lid & 7);
    const int b_gsel = ((lid >> 3) & 1);

    const float* bs = (const float*)(smem + OFF_BIAS);
    const int rl = lid >> 2;
    const int cl = (lid & 3) * 2;

    int buf = 0;
    for (; tile < ntiles; tile += gridDim.x) {
        const int next_tile = tile + (int)gridDim.x;
        #pragma unroll
        for (int j = 0; j < NSLOT; ++j) {
            // prefetch next tile's indices mid-stream
            if (j == 3 && next_tile < ntiles) load_idxs(next_tile, nidxs);

            const bool has_next = (j < NSLOT - 1) || (next_tile < ntiles);
            if (has_next) {
                const int src_row = (j < NSLOT - 1) ? idxs[j + 1] : nidxs[0];
                stage_A(src_row, buf ^ 1);
                CP_COMMIT();
                asm volatile("cp.async.wait_group 1;" ::: "memory");
            } else {
                asm volatile("cp.async.wait_group 0;" ::: "memory");
            }
            __syncthreads();   // A[buf] (+W on first pass) visible

            const uint32_t wbase = sb + OFF_W + (uint32_t)j * 32768u;
            const uint32_t abase = sb + OFF_A + (uint32_t)buf * 32768u;
            #pragma unroll
            for (int kc = 0; kc < 8; ++kc) {
                uint32_t bh[4][2];
                const int gB = kc * 2 + b_gsel;
                #pragma unroll
                for (int nt = 0; nt < 4; ++nt) {
                    const int nr = wn * 32 + nt * 8 + b_row;
                    const uint32_t off =
                        (uint32_t)nr * 256u + (((uint32_t)(gB ^ (nr & 7))) << 4);
                    ldsm_x2(bh[nt], wbase + off);
                }
                const int gA = kc * 2 + a_gsel;
                #pragma unroll
                for (int mt = 0; mt < 2; ++mt) {
                    const int ar = wm * 32 + mt * 16 + a_row;
                    const uint32_t off =
                        (uint32_t)ar * 256u + (((uint32_t)(gA ^ (ar & 7))) << 4);
                    uint32_t ah[4];
                    ldsm_x4(ah, abase + off);
                    #pragma unroll
                    for (int nt = 0; nt < 4; ++nt)
                        mma16816(acc[mt][nt], ah, bh[nt]);
                }
            }
            __syncthreads();   // all warps done reading A[buf] before reuse
            buf ^= 1;
        }

        // ---- epilogue: overlaps next tile's slot-0 staging (already in flight) --
        const int row0 = tile * 128;
        #pragma unroll
        for (int mt = 0; mt < 2; ++mt) {
            const int r_base = row0 + wm * 32 + mt * 16 + rl;
            #pragma unroll
            for (int nt = 0; nt < 4; ++nt) {
                const int col = wn * 32 + nt * 8 + cl;
                const float b0 = bs[col], b1 = bs[col + 1];
                if (r_base < N) {
                    float2 vv = make_float2(acc[mt][nt][0] + b0,
                                            acc[mt][nt][1] + b1);
                    *(float2*)(out + (size_t)r_base * 128 + col) = vv;
                }
                if (r_base + 8 < N) {
                    float2 vv = make_float2(acc[mt][nt][2] + b0,
                                            acc[mt][nt][3] + b1);
                    *(float2*)(out + (size_t)(r_base + 8) * 128 + col) = vv;
                }
                #pragma unroll
                for (int q = 0; q < 4; ++q) acc[mt][nt][q] = 0.0f;
            }
        }

        // roll prefetched indices
        #pragma unroll
        for (int k = 0; k < NSLOT; ++k) idxs[k] = nidxs[k];
    }
}

// ---- launch ------------------------------------------------------------------
extern "C" void kernel_launch(void* const* d_in, const int* in_sizes, int n_in,
                              void* d_out, int out_size) {
    const float* x   = (const float*)d_in[0];
    const void*  nbr = d_in[1];
    const float* W   = (const float*)d_in[2];
    const float* b   = (const float*)d_in[3];
    float* out = (float*)d_out;
    const int N = in_sizes[0] / 128;
    const int ngroups = N * 16;   // 8 fp32 elems per group

    cudaFuncSetAttribute(mcconv_kernel,
                         cudaFuncAttributeMaxDynamicSharedMemorySize, SMEM_BYTES);

    prep_kernel<<<(ngroups + 255) / 256, 256>>>(x, W, (const int*)nbr, ngroups);
    mcconv_kernel<<<148, 512, SMEM_BYTES>>>(nbr, b, out, N);
}

// round 10
// speedup vs baseline: 1.4271x; 1.0448x over previous
#include <cuda_runtime.h>
#include <cuda_fp16.h>
#include <cstdint>

// ============================================================================
// MotherCubeConv: y[n] = concat(x[n], x[nbr0..3(n)]) @ W^T + b
//   N=200000, F_in=128, fan_in=640, F_out=128.
// fp16 mma.sync. R10: persistent CTAs with ONE barrier per slot:
//   wait(A_j) -> sync -> stage A_{j+1} (overlaps MMA) -> MMA_j
// W resident (160KB, staged once); A double-buffered; 512 thr, 32x32 tiles.
// ============================================================================

#define NSLOT 5
#define MAX_ROWS 200704

// ---- scratch (__device__ globals; no allocation allowed) -------------------
__device__ uint4 g_Wh[NSLOT * 2048];            // 5 x [128x128] fp16, swizzled
__device__ uint4 g_x16[(size_t)MAX_ROWS * 16];  // fp16 image of x (51.4MB)
__device__ int   g_is64;

// ---- helpers ----------------------------------------------------------------
__device__ __forceinline__ uint32_t smem_u32(const void* p) {
    uint32_t a;
    asm("{ .reg .u64 t; cvta.to.shared.u64 t, %1; cvt.u32.u64 %0, t; }"
        : "=r"(a) : "l"(p));
    return a;
}

__device__ __forceinline__ void ldsm_x4(uint32_t* r, uint32_t addr) {
    asm volatile("ldmatrix.sync.aligned.m8n8.x4.shared.b16 {%0,%1,%2,%3}, [%4];"
                 : "=r"(r[0]), "=r"(r[1]), "=r"(r[2]), "=r"(r[3]) : "r"(addr));
}
__device__ __forceinline__ void ldsm_x2(uint32_t* r, uint32_t addr) {
    asm volatile("ldmatrix.sync.aligned.m8n8.x2.shared.b16 {%0,%1}, [%2];"
                 : "=r"(r[0]), "=r"(r[1]) : "r"(addr));
}

__device__ __forceinline__ void mma16816(float* d, const uint32_t* a,
                                         const uint32_t* b) {
    asm volatile(
        "mma.sync.aligned.m16n8k16.row.col.f32.f16.f16.f32 "
        "{%0,%1,%2,%3}, {%4,%5,%6,%7}, {%8,%9}, {%0,%1,%2,%3};"
        : "+f"(d[0]), "+f"(d[1]), "+f"(d[2]), "+f"(d[3])
        : "r"(a[0]), "r"(a[1]), "r"(a[2]), "r"(a[3]), "r"(b[0]), "r"(b[1]));
}

#define CP_ASYNC16(dst, src) \
    asm volatile("cp.async.cg.shared.global [%0], [%1], 16;" \
                 :: "r"(dst), "l"(src) : "memory")
#define CP_COMMIT() asm volatile("cp.async.commit_group;" ::: "memory")

// Swizzled byte offset: 256B row stride (16 groups of 16B), group XOR row&7.
__device__ __host__ __forceinline__ uint32_t tile_off(int row, int k) {
    uint32_t g = (uint32_t)(k >> 3);
    return (uint32_t)row * 256u + (((g ^ (uint32_t)(row & 7)) << 4)) +
           (uint32_t)(k & 7) * 2u;
}

// ---- fused prologue: cvt x -> fp16 image, W -> fp16 swizzled, dtype detect --
__global__ void prep_kernel(const float* __restrict__ x,
                            const float* __restrict__ W,
                            const int* __restrict__ nbr, int ngroups) {
    const int t = blockIdx.x * blockDim.x + threadIdx.x;
    if (t < ngroups) {
        const float4* s = (const float4*)x + (size_t)t * 2;
        float4 a = s[0], b = s[1];
        __half2 h0 = __floats2half2_rn(a.x, a.y);
        __half2 h1 = __floats2half2_rn(a.z, a.w);
        __half2 h2 = __floats2half2_rn(b.x, b.y);
        __half2 h3 = __floats2half2_rn(b.z, b.w);
        uint4 u;
        u.x = *(uint32_t*)&h0; u.y = *(uint32_t*)&h1;
        u.z = *(uint32_t*)&h2; u.w = *(uint32_t*)&h3;
        g_x16[t] = u;
    }
    if (t < NSLOT * 128 * 64) {
        int cp = t & 63;
        int f  = (t >> 6) & 127;
        int j  = t >> 13;
        int k  = cp * 2;
        __half2 h = __floats2half2_rn(W[f * 640 + j * 128 + k],
                                      W[f * 640 + j * 128 + k + 1]);
        *(uint32_t*)((char*)g_Wh + (size_t)j * 32768 + tile_off(f, k)) =
            *(uint32_t*)&h;
    }
    if (t == 0) {
        int all0 = 1;
        for (int i = 0; i < 64; i++)
            if (nbr[2 * i + 1] != 0) { all0 = 0; break; }
        g_is64 = all0;
    }
}

// ---- SMEM layout --------------------------------------------------------------
static constexpr uint32_t OFF_BIAS = 0;        // 512B
static constexpr uint32_t OFF_W    = 1024;     // 5 x 32KB (resident)
static constexpr uint32_t OFF_A    = 164864;   // 2 x 32KB
static constexpr uint32_t SMEM_BYTES = 230400;

__global__ void __launch_bounds__(512, 1)
mcconv_kernel(const void* __restrict__ nbr_raw,
              const float* __restrict__ bias_g, float* __restrict__ out, int N) {
    extern __shared__ char smem[];
    const uint32_t sb = smem_u32(smem);
    const int tid = threadIdx.x;
    const int wid = tid >> 5;
    const int lid = tid & 31;
    const int ntiles = (N + 127) >> 7;

    if (tid < 128) ((float*)(smem + OFF_BIAS))[tid] = bias_g[tid];

    // ---- stage all W (160KB) once ---------------------------------------------
    {
        const char* src = (const char*)g_Wh;
        const uint32_t dst = sb + OFF_W;
        #pragma unroll
        for (int w = 0; w < 20; ++w) {
            const uint32_t e = (uint32_t)(tid + w * 512) * 16u;
            CP_ASYNC16(dst + e, src + e);
        }
    }

    const int r    = tid >> 2;            // tile row 0..127 this thread stages
    const int c0   = (tid & 3) * 4;       // first of 4 16B-chunks (of 16)
    const int is64 = g_is64;
    const long long* nbr64 = (const long long*)nbr_raw;
    const int*       nbr32 = (const int*)nbr_raw;

    auto load_idxs = [&](int tile, int* dst) {
        const int grow = tile * 128 + r;
        const bool v = grow < N;
        const int base = v ? grow : 0;
        dst[0] = base;
        if (is64) {
            const long long* p = nbr64 + (size_t)base * 4;
            #pragma unroll
            for (int k = 0; k < 4; ++k) dst[k + 1] = v ? (int)p[k] : 0;
        } else {
            const int* p = nbr32 + (size_t)base * 4;
            #pragma unroll
            for (int k = 0; k < 4; ++k) dst[k + 1] = v ? p[k] : 0;
        }
    };

    auto stage_A = [&](int src_row, int buf) {
        const char* src = (const char*)g_x16 + (size_t)src_row * 256;
        const uint32_t dst = sb + OFF_A + (uint32_t)buf * 32768u;
        #pragma unroll
        for (int c = 0; c < 4; ++c) {
            const int chunk = c0 + c;
            CP_ASYNC16(dst + tile_off(r, chunk * 8), src + chunk * 16);
        }
    };

    int idxs[NSLOT], nidxs[NSLOT];
    int tile = blockIdx.x;
    if (tile < ntiles) {
        load_idxs(tile, idxs);
        stage_A(idxs[0], 0);
    }
    CP_COMMIT();   // group: W + A(tile0, slot0)

    // warp tiling: 4 (M) x 4 (N); warp tile = 32 rows x 32 cols
    const int wm = wid >> 2;
    const int wn = wid & 3;

    float acc[2][4][4];
    #pragma unroll
    for (int mt = 0; mt < 2; ++mt)
        #pragma unroll
        for (int nt = 0; nt < 4; ++nt)
            #pragma unroll
            for (int q = 0; q < 4; ++q) acc[mt][nt][q] = 0.0f;

    const int a_row  = (lid & 15);
    const int a_gsel = (lid >> 4);
    const int b_row  = (lid & 7);
    const int b_gsel = ((lid >> 3) & 1);

    // hoist per-warp bias values (tile-invariant) into registers
    const int rl = lid >> 2;
    const int cl = (lid & 3) * 2;
    float bias0[4], bias1[4];
    __syncthreads();   // bias smem stores visible
    #pragma unroll
    for (int nt = 0; nt < 4; ++nt) {
        const int col = wn * 32 + nt * 8 + cl;
        bias0[nt] = ((const float*)(smem + OFF_BIAS))[col];
        bias1[nt] = ((const float*)(smem + OFF_BIAS))[col + 1];
    }

    int buf = 0;
    for (; tile < ntiles; tile += gridDim.x) {
        const int next_tile = tile + (int)gridDim.x;
        #pragma unroll
        for (int j = 0; j < NSLOT; ++j) {
            // prefetch next tile's indices mid-stream
            if (j == 3 && next_tile < ntiles) load_idxs(next_tile, nidxs);

            asm volatile("cp.async.wait_group 0;" ::: "memory");  // A_j landed
            __syncthreads();   // all warps done with buf^1; A[buf] visible

            // stage next slot into buf^1 — overlaps this slot's MMA phase
            const bool has_next = (j < NSLOT - 1) || (next_tile < ntiles);
            if (has_next) {
                const int src_row = (j < NSLOT - 1) ? idxs[j + 1] : nidxs[0];
                stage_A(src_row, buf ^ 1);
                CP_COMMIT();
            }

            const uint32_t wbase = sb + OFF_W + (uint32_t)j * 32768u;
            const uint32_t abase = sb + OFF_A + (uint32_t)buf * 32768u;
            #pragma unroll
            for (int kc = 0; kc < 8; ++kc) {
                uint32_t bh[4][2];
                const int gB = kc * 2 + b_gsel;
                #pragma unroll
                for (int nt = 0; nt < 4; ++nt) {
                    const int nr = wn * 32 + nt * 8 + b_row;
                    const uint32_t off =
                        (uint32_t)nr * 256u + (((uint32_t)(gB ^ (nr & 7))) << 4);
                    ldsm_x2(bh[nt], wbase + off);
                }
                const int gA = kc * 2 + a_gsel;
                #pragma unroll
                for (int mt = 0; mt < 2; ++mt) {
                    const int ar = wm * 32 + mt * 16 + a_row;
                    const uint32_t off =
                        (uint32_t)ar * 256u + (((uint32_t)(gA ^ (ar & 7))) << 4);
                    uint32_t ah[4];
                    ldsm_x4(ah, abase + off);
                    #pragma unroll
                    for (int nt = 0; nt < 4; ++nt)
                        mma16816(acc[mt][nt], ah, bh[nt]);
                }
            }
            buf ^= 1;
        }

        // ---- epilogue (overlaps next tile's slot-0 staging, already in flight) --
        const int row0 = tile * 128;
        #pragma unroll
        for (int mt = 0; mt < 2; ++mt) {
            const int r_base = row0 + wm * 32 + mt * 16 + rl;
            #pragma unroll
            for (int nt = 0; nt < 4; ++nt) {
                const int col = wn * 32 + nt * 8 + cl;
                if (r_base < N) {
                    float2 vv = make_float2(acc[mt][nt][0] + bias0[nt],
                                            acc[mt][nt][1] + bias1[nt]);
                    *(float2*)(out + (size_t)r_base * 128 + col) = vv;
                }
                if (r_base + 8 < N) {
                    float2 vv = make_float2(acc[mt][nt][2] + bias0[nt],
                                            acc[mt][nt][3] + bias1[nt]);
                    *(float2*)(out + (size_t)(r_base + 8) * 128 + col) = vv;
                }
                #pragma unroll
                for (int q = 0; q < 4; ++q) acc[mt][nt][q] = 0.0f;
            }
        }

        // roll prefetched indices
        #pragma unroll
        for (int k = 0; k < NSLOT; ++k) idxs[k] = nidxs[k];
    }
}

// ---- launch ------------------------------------------------------------------
extern "C" void kernel_launch(void* const* d_in, const int* in_sizes, int n_in,
                              void* d_out, int out_size) {
    const float* x   = (const float*)d_in[0];
    const void*  nbr = d_in[1];
    const float* W   = (const float*)d_in[2];
    const float* b   = (const float*)d_in[3];
    float* out = (float*)d_out;
    const int N = in_sizes[0] / 128;
    const int ngroups = N * 16;   // 8 fp32 elems per group

    cudaFuncSetAttribute(mcconv_kernel,
                         cudaFuncAttributeMaxDynamicSharedMemorySize, SMEM_BYTES);

    prep_kernel<<<(ngroups + 255) / 256, 256>>>(x, W, (const int*)nbr, ngroups);
    mcconv_kernel<<<148, 512, SMEM_BYTES>>>(nbr, b, out, N);
}